// round 17
// baseline (speedup 1.0000x reference)
#include <cuda_runtime.h>
#include <cuda_fp16.h>
#include <cstdint>

// C[2048,4096] = A[2048,4096] @ W[4096,4096]^T + bias
// W dequantized from 4-bit codebook codes.
// R17: fused producer/consumer kernel. 296 CTAs (all resident on 148 SMs x 2):
// CTAs 0-79 dequant W + convert A (per-strip arrival counters), all CTAs then
// consume 128x128 output tiles from a ticket counter, spinning on the strip
// flags. Tile body = R8 (BK=32, 3-stage cp.async wait_group 1, ldmatrix,
// fp16 mma, direct bias epilogue). Prep overlaps the gemm.

constexpr int KDIM = 4096;
constexpr int NDIM = 4096;
constexpr int MDIM = 2048;

__device__ __half g_W[(size_t)NDIM * KDIM];   // dequantized fp16
__device__ __half g_A[(size_t)MDIM * KDIM];   // activations fp16

__device__ int g_wcnt[32];    // W strip arrival counters (target 80)
__device__ int g_acnt[16];    // A strip arrival counters (target 80)
__device__ int g_tctr;        // tile ticket counter

constexpr int NPREP = 80;     // producer CTAs
constexpr int NCTAS = 296;    // total CTAs (<= 148 SMs x 2 -> all resident)
constexpr int NTILES = 512;   // 32 x 16 tiles of 128x128

// ---------------------------------------------------------------------------
__global__ void reset_kernel() {
    if (threadIdx.x < 32) g_wcnt[threadIdx.x] = 0;
    if (threadIdx.x < 16) g_acnt[threadIdx.x] = 0;
    if (threadIdx.x == 0) g_tctr = 0;
}

// ---------------------------------------------------------------------------
// GEMM tile config (identical to R8)
// ---------------------------------------------------------------------------
constexpr int BM = 128, BN = 128, BK = 32;
constexpr int NTHREADS = 128;
constexpr int STRIDE = 40;                            // halfs; bank-bijective
constexpr int A_STAGE = BM * STRIDE;                  // 5120 halfs
constexpr int B_STAGE = BN * STRIDE;                  // 5120 halfs
constexpr int STAGE   = A_STAGE + B_STAGE;            // 10240 halfs (20480 B)
constexpr int NSTAGE  = 3;
constexpr int SMEM_DYN = STAGE * NSTAGE * 2;          // 61440 bytes
constexpr int KITERS = KDIM / BK;                     // 128

extern __shared__ __half smh[];

__device__ __forceinline__ uint32_t smem_u32(const void* p) {
    uint32_t a;
    asm("{ .reg .u64 t; cvta.to.shared.u64 t, %1; cvt.u32.u64 %0, t; }"
        : "=r"(a) : "l"(p));
    return a;
}

__device__ __forceinline__ void cp_async16(uint32_t dst, const void* src) {
    asm volatile("cp.async.cg.shared.global [%0], [%1], 16;"
                 :: "r"(dst), "l"(src));
}

__device__ __forceinline__ void ldmatrix_x4(uint32_t* r, uint32_t addr) {
    asm volatile(
        "ldmatrix.sync.aligned.m8n8.x4.shared.b16 {%0, %1, %2, %3}, [%4];"
        : "=r"(r[0]), "=r"(r[1]), "=r"(r[2]), "=r"(r[3])
        : "r"(addr));
}

__device__ __forceinline__ void mma_f16(float* c, const uint32_t* a,
                                        const uint32_t* b) {
    asm volatile(
        "mma.sync.aligned.m16n8k16.row.col.f32.f16.f16.f32 "
        "{%0,%1,%2,%3}, {%4,%5,%6,%7}, {%8,%9}, {%0,%1,%2,%3};"
        : "+f"(c[0]), "+f"(c[1]), "+f"(c[2]), "+f"(c[3])
        : "r"(a[0]), "r"(a[1]), "r"(a[2]), "r"(a[3]), "r"(b[0]), "r"(b[1]));
}

__device__ __forceinline__ void load_tile(uint32_t sbase,
                                          const __half* __restrict__ Ab,
                                          const __half* __restrict__ Bb,
                                          int k0, int tid) {
    #pragma unroll
    for (int j = 0; j < 4; j++) {
        int i = tid + j * NTHREADS;
        int row = i >> 2, c = (i & 3) * 8;
        cp_async16(sbase + (uint32_t)(row * STRIDE + c) * 2,
                   Ab + (size_t)row * KDIM + k0 + c);
    }
    const uint32_t sb = sbase + A_STAGE * 2;
    #pragma unroll
    for (int j = 0; j < 4; j++) {
        int i = tid + j * NTHREADS;
        int row = i >> 2, c = (i & 3) * 8;
        cp_async16(sb + (uint32_t)(row * STRIDE + c) * 2,
                   Bb + (size_t)row * KDIM + k0 + c);
    }
    asm volatile("cp.async.commit_group;" ::: "memory");
}

// ---------------------------------------------------------------------------
__global__ void __launch_bounds__(NTHREADS, 2)
fused_kernel(const float* __restrict__ codebooks,
             const int* __restrict__ codes,
             const float* __restrict__ x,
             const float* __restrict__ bias,
             float* __restrict__ C) {
    const int tid  = threadIdx.x;
    const int wid  = tid >> 5;
    const int lane = tid & 31;
    const int gid  = lane >> 2;
    const int tig  = lane & 3;

    // ---------------- producer phase (CTAs 0..79) ----------------
    if (blockIdx.x < NPREP) {
        const int p = blockIdx.x;
        const bool two = (p < 48);

        // A strips first (16 strips x 128 rows)
        for (int s = 0; s < 16; s++) {
            const int r0 = 128 * s + p;
            const int r1 = r0 + NPREP;
            const float4* x4 = (const float4*)x;
            float4 va[8], vb[8];
            #pragma unroll
            for (int j = 0; j < 8; j++)
                va[j] = x4[(size_t)r0 * 1024 + tid * 8 + j];
            if (two) {
                #pragma unroll
                for (int j = 0; j < 8; j++)
                    vb[j] = x4[(size_t)r1 * 1024 + tid * 8 + j];
            }
            alignas(16) __half2 h[16];
            #pragma unroll
            for (int j = 0; j < 8; j++) {
                h[2 * j]     = __floats2half2_rn(va[j].x, va[j].y);
                h[2 * j + 1] = __floats2half2_rn(va[j].z, va[j].w);
            }
            uint4* a4 = (uint4*)(g_A + (size_t)r0 * KDIM);
            #pragma unroll
            for (int j = 0; j < 4; j++) a4[tid * 4 + j] = ((uint4*)h)[j];
            if (two) {
                #pragma unroll
                for (int j = 0; j < 8; j++) {
                    h[2 * j]     = __floats2half2_rn(vb[j].x, vb[j].y);
                    h[2 * j + 1] = __floats2half2_rn(vb[j].z, vb[j].w);
                }
                uint4* b4 = (uint4*)(g_A + (size_t)r1 * KDIM);
                #pragma unroll
                for (int j = 0; j < 4; j++) b4[tid * 4 + j] = ((uint4*)h)[j];
            }
            __threadfence();
            __syncthreads();
            if (tid == 0) atomicAdd(&g_acnt[s], 1);
        }

        // W strips (32 strips x 128 rows), codebook staged in smem
        float* cb0 = (float*)smh;          // 512 floats
        float* cb1 = cb0 + 512;            // 512 floats
        for (int s = 0; s < 32; s++) {
            const int r0 = 128 * s + p;
            const int r1 = r0 + NPREP;
            {
                const float4* c4 = (const float4*)(codebooks + (size_t)r0 * 512);
                ((float4*)cb0)[tid] = c4[tid];
                if (two) {
                    const float4* d4 = (const float4*)(codebooks + (size_t)r1 * 512);
                    ((float4*)cb1)[tid] = d4[tid];
                }
            }
            __syncthreads();

            const int4* cr0 = (const int4*)(codes + (size_t)r0 * KDIM);
            int4 c[8], d[8];
            #pragma unroll
            for (int j = 0; j < 8; j++) c[j] = cr0[tid * 8 + j];
            if (two) {
                const int4* cr1 = (const int4*)(codes + (size_t)r1 * KDIM);
                #pragma unroll
                for (int j = 0; j < 8; j++) d[j] = cr1[tid * 8 + j];
            }

            alignas(16) __half2 h[16];
            const float* g0 = cb0 + ((tid >> 2) << 4);
            #pragma unroll
            for (int j = 0; j < 8; j++) {
                h[2 * j]     = __floats2half2_rn(g0[c[j].x], g0[c[j].y]);
                h[2 * j + 1] = __floats2half2_rn(g0[c[j].z], g0[c[j].w]);
            }
            uint4* w4 = (uint4*)(g_W + (size_t)r0 * KDIM);
            #pragma unroll
            for (int j = 0; j < 4; j++) w4[tid * 4 + j] = ((uint4*)h)[j];
            if (two) {
                const float* g1 = cb1 + ((tid >> 2) << 4);
                #pragma unroll
                for (int j = 0; j < 8; j++) {
                    h[2 * j]     = __floats2half2_rn(g1[d[j].x], g1[d[j].y]);
                    h[2 * j + 1] = __floats2half2_rn(g1[d[j].z], g1[d[j].w]);
                }
                uint4* v4 = (uint4*)(g_W + (size_t)r1 * KDIM);
                #pragma unroll
                for (int j = 0; j < 4; j++) v4[tid * 4 + j] = ((uint4*)h)[j];
            }
            __threadfence();
            __syncthreads();
            if (tid == 0) atomicAdd(&g_wcnt[s], 1);
        }
        __syncthreads();   // smem (cb region) free before gemm use
    }

    // ---------------- consumer phase (all CTAs) ----------------
    const uint32_t smem_base = smem_u32(smh);
    const uint32_t a_lane = (uint32_t)((lane & 15) * STRIDE + ((lane >> 4) << 3)) * 2;
    const uint32_t b_lane = (uint32_t)((((lane >> 4) << 3) + (lane & 7)) * STRIDE
                                       + (lane & 8)) * 2;
    const int wm = (wid >> 1) * 64;
    const int wn = (wid & 1) * 64;

    __shared__ int sh_t;
    for (;;) {
        if (tid == 0) sh_t = atomicAdd(&g_tctr, 1);
        __syncthreads();
        const int t = sh_t;
        if (t >= NTILES) break;
        const int bx = t >> 4;          // n-block / W strip
        const int by = t & 15;          // m-block / A strip

        if (tid == 0) {
            while (*(volatile int*)&g_wcnt[bx] < NPREP ||
                   *(volatile int*)&g_acnt[by] < NPREP)
                __nanosleep(128);
            __threadfence();
        }
        __syncthreads();

        const int m0 = by * BM;
        const int n0 = bx * BN;
        const __half* Ab = g_A + (size_t)m0 * KDIM;
        const __half* Bb = g_W + (size_t)n0 * KDIM;

        float acc[4][8][4] = {};

        load_tile(smem_base,             Ab, Bb, 0,  tid);
        load_tile(smem_base + STAGE * 2, Ab, Bb, BK, tid);

        for (int it = 0; it < KITERS; it++) {
            if (it + 1 < KITERS) {
                asm volatile("cp.async.wait_group 1;" ::: "memory");
            } else {
                asm volatile("cp.async.wait_group 0;" ::: "memory");
            }
            __syncthreads();

            if (it + 2 < KITERS) {
                load_tile(smem_base + (uint32_t)((it + 2) % NSTAGE) * STAGE * 2,
                          Ab, Bb, (it + 2) * BK, tid);
            }

            const uint32_t sA = smem_base + (uint32_t)(it % NSTAGE) * STAGE * 2;
            const uint32_t sB = sA + A_STAGE * 2;

            #pragma unroll
            for (int ks = 0; ks < 2; ks++) {
                const int kb = ks * 16;
                uint32_t af[4][4], bf[4][4];
                #pragma unroll
                for (int mt = 0; mt < 4; mt++) {
                    ldmatrix_x4(af[mt],
                                sA + (uint32_t)((wm + mt * 16) * STRIDE + kb) * 2
                                   + a_lane);
                }
                #pragma unroll
                for (int pq = 0; pq < 4; pq++) {
                    ldmatrix_x4(bf[pq],
                                sB + (uint32_t)((wn + pq * 16) * STRIDE + kb) * 2
                                   + b_lane);
                }
                #pragma unroll
                for (int mt = 0; mt < 4; mt++) {
                    #pragma unroll
                    for (int pq = 0; pq < 4; pq++) {
                        mma_f16(acc[mt][2 * pq],     af[mt], &bf[pq][0]);
                        mma_f16(acc[mt][2 * pq + 1], af[mt], &bf[pq][2]);
                    }
                }
            }
        }

        // epilogue: bias + store
        #pragma unroll
        for (int mt = 0; mt < 4; mt++) {
            #pragma unroll
            for (int nt = 0; nt < 8; nt++) {
                const int r0 = m0 + wm + mt * 16 + gid;
                const int cc = n0 + wn + nt * 8 + tig * 2;
                const float2 b2 = *(const float2*)(bias + cc);
                float2 o0, o1;
                o0.x = acc[mt][nt][0] + b2.x;
                o0.y = acc[mt][nt][1] + b2.y;
                o1.x = acc[mt][nt][2] + b2.x;
                o1.y = acc[mt][nt][3] + b2.y;
                *(float2*)(C + (size_t)r0 * NDIM + cc)       = o0;
                *(float2*)(C + (size_t)(r0 + 8) * NDIM + cc) = o1;
            }
        }
        __syncthreads();   // smem safe for next tile's prologue
    }
}

// ---------------------------------------------------------------------------
extern "C" void kernel_launch(void* const* d_in, const int* in_sizes, int n_in,
                              void* d_out, int out_size) {
    const float* x         = (const float*)d_in[0];
    const float* codebooks = (const float*)d_in[1];
    const int*   codes     = (const int*)d_in[2];
    const float* bias      = (const float*)d_in[3];
    float* out = (float*)d_out;

    reset_kernel<<<1, 32>>>();

    cudaFuncSetAttribute(fused_kernel,
                         cudaFuncAttributeMaxDynamicSharedMemorySize, SMEM_DYN);
    fused_kernel<<<NCTAS, NTHREADS, SMEM_DYN>>>(codebooks, codes, x, bias, out);
}